// round 9
// baseline (speedup 1.0000x reference)
#include <cuda_runtime.h>
#include <cuda_fp16.h>
#include <cstdint>

#define B_ROWS 32768
#define D1 1024
#define D2 512
#define KTOT 1536
#define OUTD 1024
#define NPACK 2048

// scratch (allocation-free rule: __device__ globals)
__device__ __align__(128) __half g_f[(size_t)B_ROWS * KTOT];  // 96 MB activations
__device__ __align__(128) __half g_w[(size_t)NPACK * KTOT];   // 6 MB packed W^T

__device__ __forceinline__ float leaky(float x) { return x >= 0.f ? x : 0.01f * x; }

// ---------------------------------------------------------------------------
// Kernel 1 (merged): blocks 0..4095 = LayerNorm+leaky (warp-per-row, shfl);
// blocks 4096..7167 = weight pack. Independent work, one launch.
// pack: col c: q=c>>5, r=c&31, n=q*16+(r&15); r<16 -> W_out else W_g.
// ---------------------------------------------------------------------------
#define LN_BLOCKS (B_ROWS / 8)          // 4096
#define PK_BLOCKS (64 * 48)             // 3072

__global__ void __launch_bounds__(256) prologue_kernel(
    const float* __restrict__ x1, const float* __restrict__ x2,
    const float* __restrict__ s1, const float* __restrict__ b1,
    const float* __restrict__ s2, const float* __restrict__ b2,
    const float* __restrict__ Wo1, const float* __restrict__ Wo2,
    const float* __restrict__ Wg1, const float* __restrict__ Wg2) {
    __shared__ __half smp[32][40];
    if (blockIdx.x >= LN_BLOCKS) {
        // ---- weight pack ----
        int pid = blockIdx.x - LN_BLOCKS;
        int q = pid & 63;
        int kt = pid >> 6;
        int t = threadIdx.x;
        int r = t & 31;
        int kk = t >> 5;
        int k0 = kt * 32;
        const float* W;
        int kbase;
        if (k0 < D1) { W = (r < 16) ? Wo1 : Wg1; kbase = k0; }
        else         { W = (r < 16) ? Wo2 : Wg2; kbase = k0 - D1; }
        int n = q * 16 + (r & 15);
#pragma unroll
        for (int p = 0; p < 4; p++) {
            int kl = kk + 8 * p;
            smp[r][kl] = __float2half_rn(W[(size_t)(kbase + kl) * OUTD + n]);
        }
        __syncthreads();
        int r2 = t >> 3, j = t & 7;
        uint2 val = *reinterpret_cast<uint2*>(&smp[r2][j * 4]);
        *reinterpret_cast<uint2*>(&g_w[(size_t)(q * 32 + r2) * KTOT + k0 + j * 4]) = val;
        return;
    }

    // ---- LayerNorm + leaky_relu ----
    int lane = threadIdx.x & 31;
    int row = blockIdx.x * 8 + (threadIdx.x >> 5);

    const float4* xr = reinterpret_cast<const float4*>(x1 + (size_t)row * D1);
    float s = 0.f, q = 0.f;
#pragma unroll
    for (int j = 0; j < 8; j++) {
        float4 t = xr[lane + 32 * j];
        s += t.x + t.y + t.z + t.w;
        q += t.x*t.x + t.y*t.y + t.z*t.z + t.w*t.w;
    }
#pragma unroll
    for (int o = 16; o; o >>= 1) {
        s += __shfl_xor_sync(0xffffffffu, s, o);
        q += __shfl_xor_sync(0xffffffffu, q, o);
    }
    float m = s * (1.f / D1);
    float inv = rsqrtf(q * (1.f / D1) - m * m + 1e-6f);
    __half2* dst = reinterpret_cast<__half2*>(g_f + (size_t)row * KTOT);
#pragma unroll
    for (int j = 0; j < 8; j++) {
        int f = lane + 32 * j;
        float4 t = xr[f];
        float4 sc = reinterpret_cast<const float4*>(s1)[f];
        float4 bi = reinterpret_cast<const float4*>(b1)[f];
        float y0 = leaky((t.x - m) * inv * sc.x + bi.x);
        float y1 = leaky((t.y - m) * inv * sc.y + bi.y);
        float y2 = leaky((t.z - m) * inv * sc.z + bi.z);
        float y3 = leaky((t.w - m) * inv * sc.w + bi.w);
        dst[2 * f]     = __floats2half2_rn(y0, y1);
        dst[2 * f + 1] = __floats2half2_rn(y2, y3);
    }

    const float4* xr2 = reinterpret_cast<const float4*>(x2 + (size_t)row * D2);
    float4 w[4];
    s = 0.f; q = 0.f;
#pragma unroll
    for (int j = 0; j < 4; j++) {
        w[j] = xr2[lane + 32 * j];
        s += w[j].x + w[j].y + w[j].z + w[j].w;
        q += w[j].x*w[j].x + w[j].y*w[j].y + w[j].z*w[j].z + w[j].w*w[j].w;
    }
#pragma unroll
    for (int o = 16; o; o >>= 1) {
        s += __shfl_xor_sync(0xffffffffu, s, o);
        q += __shfl_xor_sync(0xffffffffu, q, o);
    }
    float m2 = s * (1.f / D2);
    float inv2 = rsqrtf(q * (1.f / D2) - m2 * m2 + 1e-6f);
    __half2* dst2 = reinterpret_cast<__half2*>(g_f + (size_t)row * KTOT + D1);
#pragma unroll
    for (int j = 0; j < 4; j++) {
        int f = lane + 32 * j;
        float4 sc = reinterpret_cast<const float4*>(s2)[f];
        float4 bi = reinterpret_cast<const float4*>(b2)[f];
        float y0 = leaky((w[j].x - m2) * inv2 * sc.x + bi.x);
        float y1 = leaky((w[j].y - m2) * inv2 * sc.y + bi.y);
        float y2 = leaky((w[j].z - m2) * inv2 * sc.z + bi.z);
        float y3 = leaky((w[j].w - m2) * inv2 * sc.w + bi.w);
        dst2[2 * f]     = __floats2half2_rn(y0, y1);
        dst2[2 * f + 1] = __floats2half2_rn(y2, y3);
    }
}

// ---------------------------------------------------------------------------
// Kernel 2: mma.sync GEMM 128x128p x K=1536, 256 thr, 8 warps (64x32),
// 3-stage cp.async (96KB -> 2 CTAs/SM), ldmatrix.x4, fused gate epilogue.
// Bias prefetched pre-mainloop; epilogue stores evict-first.
// ---------------------------------------------------------------------------
#define BK 64
#define KIT (KTOT / BK)          // 24
#define ST_A 16384
#define ST_B 16384
#define ST_STRIDE (ST_A + ST_B)  // 32768
#define SMEM_DYN (3 * ST_STRIDE) // 98304

__device__ __forceinline__ uint32_t smem_u32(const void* p) {
    uint32_t a;
    asm("{ .reg .u64 t; cvta.to.shared.u64 t, %1; cvt.u32.u64 %0, t; }" : "=r"(a) : "l"(p));
    return a;
}
__device__ __forceinline__ void mma16816(float* c, const uint32_t* a, const uint32_t* b) {
    asm volatile(
        "mma.sync.aligned.m16n8k16.row.col.f32.f16.f16.f32 "
        "{%0,%1,%2,%3}, {%4,%5,%6,%7}, {%8,%9}, {%0,%1,%2,%3};\n"
        : "+f"(c[0]), "+f"(c[1]), "+f"(c[2]), "+f"(c[3])
        : "r"(a[0]), "r"(a[1]), "r"(a[2]), "r"(a[3]), "r"(b[0]), "r"(b[1]));
}
#define LDSM4(r0, r1, r2, r3, addr) \
    asm volatile("ldmatrix.sync.aligned.m8n8.x4.shared.b16 {%0,%1,%2,%3}, [%4];\n" \
                 : "=r"(r0), "=r"(r1), "=r"(r2), "=r"(r3) : "r"(addr))
#define CPA16(dst, src) \
    asm volatile("cp.async.cg.shared.global [%0], [%1], 16;" :: "r"(dst), "l"(src) : "memory")
#define CP_COMMIT() asm volatile("cp.async.commit_group;" ::: "memory")

__global__ void __launch_bounds__(256, 2) gemm_kernel(
    const float* __restrict__ bo1, const float* __restrict__ bo2,
    const float* __restrict__ bg1, const float* __restrict__ bg2,
    float* __restrict__ out) {
    extern __shared__ char sm[];
    uint32_t base = smem_u32(sm);

    // raster: chunks of 32 mtiles x 16 ntiles -> A+B chunk L2-resident
    int id = blockIdx.x;
    int chunk = id >> 9;
    int rem = id & 511;
    int ntile = rem >> 5;
    int mtile = chunk * 32 + (rem & 31);
    int m0 = mtile * 128;
    int c0 = ntile * 128;

    int tid = threadIdx.x;
    int warp = tid >> 5, lane = tid & 31;
    int wm = (warp & 1) * 64;
    int wn = (warp >> 1) * 32;

    // bias prefetch (4 distinct n per thread)
    float boPF[4], bgPF[4];
    {
        int t = lane & 3;
#pragma unroll
        for (int j = 0; j < 2; j++)
#pragma unroll
            for (int p = 0; p < 2; p++) {
                int n = ntile * 64 + (wn >> 1) + j * 8 + t * 2 + p;
                boPF[j * 2 + p] = __ldg(bo1 + n) + __ldg(bo2 + n);
                bgPF[j * 2 + p] = __ldg(bg1 + n) + __ldg(bg2 + n);
            }
    }

    uint32_t aDst[4], bDst[4];
    const __half* aSrc[4];
    const __half* bSrc[4];
#pragma unroll
    for (int i = 0; i < 4; i++) {
        int idx = tid + 256 * i;
        int row = idx >> 3, c = idx & 7;
        uint32_t swz = (uint32_t)(row * 128 + ((c ^ (row & 7)) * 16));
        aDst[i] = base + swz;
        bDst[i] = base + ST_A + swz;
        aSrc[i] = g_f + (size_t)(m0 + row) * KTOT + c * 8;
        bSrc[i] = g_w + (size_t)(c0 + row) * KTOT + c * 8;
    }

#define LOAD_STAGE(j) do { \
        uint32_t _so = (uint32_t)((j) % 3) * ST_STRIDE; \
        size_t _ko = (size_t)(j) * BK; \
        _Pragma("unroll") \
        for (int _i = 0; _i < 4; _i++) { \
            CPA16(aDst[_i] + _so, aSrc[_i] + _ko); \
            CPA16(bDst[_i] + _so, bSrc[_i] + _ko); \
        } \
        CP_COMMIT(); \
    } while (0)

    uint32_t xorv = lane & 7;
    uint32_t aRowOff = (uint32_t)(wm + (lane & 15)) * 128;
    uint32_t aSel = lane >> 4;
    uint32_t bRowOff = (uint32_t)(wn + ((lane >> 4) << 3) + (lane & 7)) * 128;
    uint32_t bSel = (lane >> 3) & 1;

    float acc[4][4][4];
#pragma unroll
    for (int i = 0; i < 4; i++)
#pragma unroll
        for (int j = 0; j < 4; j++)
#pragma unroll
            for (int e = 0; e < 4; e++) acc[i][j][e] = 0.f;

    LOAD_STAGE(0);
    LOAD_STAGE(1);

    for (int kt = 0; kt < KIT; kt++) {
        asm volatile("cp.async.wait_group 1;" ::: "memory");
        __syncthreads();
        if (kt + 2 < KIT) { LOAD_STAGE(kt + 2); }
        else { CP_COMMIT(); }

        uint32_t stA = base + (uint32_t)(kt % 3) * ST_STRIDE;
        uint32_t stB = stA + ST_A;
#pragma unroll
        for (int ks = 0; ks < 4; ks++) {
            uint32_t a[4][4], b[4][2];
            uint32_t physA = ((2u * ks + aSel) ^ xorv) << 4;
            uint32_t physB = ((2u * ks + bSel) ^ xorv) << 4;
#pragma unroll
            for (int mi = 0; mi < 4; mi++)
                LDSM4(a[mi][0], a[mi][1], a[mi][2], a[mi][3],
                      stA + aRowOff + mi * 2048 + physA);
            LDSM4(b[0][0], b[0][1], b[1][0], b[1][1], stB + bRowOff + physB);
            LDSM4(b[2][0], b[2][1], b[3][0], b[3][1], stB + bRowOff + 2048 + physB);
#pragma unroll
            for (int mi = 0; mi < 4; mi++)
#pragma unroll
                for (int nj = 0; nj < 4; nj++)
                    mma16816(acc[mi][nj], a[mi], b[nj]);
        }
    }
    __syncthreads();

    // epilogue: gate in regs -> smem (stride 68) -> coalesced float4 stores
    float* ep = reinterpret_cast<float*>(sm);
    {
        int g = lane >> 2, t = lane & 3;
#pragma unroll
        for (int j = 0; j < 2; j++) {
#pragma unroll
            for (int e = 0; e < 4; e++) {
                int nl = (wn >> 1) + j * 8 + t * 2 + (e & 1);
                float bo = boPF[j * 2 + (e & 1)];
                float bg = bgPF[j * 2 + (e & 1)];
#pragma unroll
                for (int mi = 0; mi < 4; mi++) {
                    int ml = wm + mi * 16 + g + ((e >> 1) * 8);
                    float o = acc[mi][j][e] + bo;
                    float gg = acc[mi][j + 2][e] + bg;
                    ep[ml * 68 + nl] = o * (1.f / (1.f + __expf(-gg)));
                }
            }
        }
    }
    __syncthreads();
    {
        float* outp = out + (size_t)m0 * OUTD + ntile * 64;
#pragma unroll
        for (int qq = 0; qq < 8; qq++) {
            int idx = tid + 256 * qq;
            int row = idx >> 4, c = (idx & 15) * 4;
            const float* src = ep + row * 68 + c;
            float4 v = make_float4(src[0], src[1], src[2], src[3]);
            __stcs(reinterpret_cast<float4*>(outp + (size_t)row * OUTD + c), v);
        }
    }
#undef LOAD_STAGE
}

// ---------------------------------------------------------------------------
extern "C" void kernel_launch(void* const* d_in, const int* in_sizes, int n_in,
                              void* d_out, int out_size) {
    const float* x1  = (const float*)d_in[0];
    const float* x2  = (const float*)d_in[1];
    const float* s1  = (const float*)d_in[2];
    const float* b1  = (const float*)d_in[3];
    const float* s2  = (const float*)d_in[4];
    const float* b2  = (const float*)d_in[5];
    const float* Wo1 = (const float*)d_in[6];
    const float* bo1 = (const float*)d_in[7];
    const float* Wo2 = (const float*)d_in[8];
    const float* bo2 = (const float*)d_in[9];
    const float* Wg1 = (const float*)d_in[10];
    const float* bg1 = (const float*)d_in[11];
    const float* Wg2 = (const float*)d_in[12];
    const float* bg2 = (const float*)d_in[13];
    float* out = (float*)d_out;

    prologue_kernel<<<LN_BLOCKS + PK_BLOCKS, 256>>>(
        x1, x2, s1, b1, s2, b2, Wo1, Wo2, Wg1, Wg2);

    cudaFuncSetAttribute(gemm_kernel,
                         cudaFuncAttributeMaxDynamicSharedMemorySize, SMEM_DYN);
    gemm_kernel<<<(B_ROWS / 128) * (NPACK / 128), 256, SMEM_DYN>>>(
        bo1, bo2, bg1, bg2, out);
}

// round 10
// speedup vs baseline: 1.0247x; 1.0247x over previous
#include <cuda_runtime.h>
#include <cuda_fp16.h>
#include <cstdint>

#define B_ROWS 32768
#define D1 1024
#define D2 512
#define KTOT 1536
#define OUTD 1024
#define NPACK 2048

// scratch (allocation-free rule: __device__ globals)
__device__ __align__(128) __half g_f[(size_t)B_ROWS * KTOT];  // 96 MB activations
__device__ __align__(128) __half g_w[(size_t)NPACK * KTOT];   // 6 MB packed W^T

__device__ __forceinline__ float leaky(float x) { return x >= 0.f ? x : 0.01f * x; }

// ---------------------------------------------------------------------------
// Kernel 1 (merged): blocks 0..4095 = LayerNorm+leaky (warp-per-row, shfl);
// blocks 4096..7167 = weight pack. Independent work, one launch.
// pack: col c: q=c>>5, r=c&31, n=q*16+(r&15); r<16 -> W_out else W_g.
// ---------------------------------------------------------------------------
#define LN_BLOCKS (B_ROWS / 8)          // 4096
#define PK_BLOCKS (64 * 48)             // 3072

__global__ void __launch_bounds__(256) prologue_kernel(
    const float* __restrict__ x1, const float* __restrict__ x2,
    const float* __restrict__ s1, const float* __restrict__ b1,
    const float* __restrict__ s2, const float* __restrict__ b2,
    const float* __restrict__ Wo1, const float* __restrict__ Wo2,
    const float* __restrict__ Wg1, const float* __restrict__ Wg2) {
    __shared__ __half smp[32][40];
    if (blockIdx.x >= LN_BLOCKS) {
        // ---- weight pack ----
        int pid = blockIdx.x - LN_BLOCKS;
        int q = pid & 63;
        int kt = pid >> 6;
        int t = threadIdx.x;
        int r = t & 31;
        int kk = t >> 5;
        int k0 = kt * 32;
        const float* W;
        int kbase;
        if (k0 < D1) { W = (r < 16) ? Wo1 : Wg1; kbase = k0; }
        else         { W = (r < 16) ? Wo2 : Wg2; kbase = k0 - D1; }
        int n = q * 16 + (r & 15);
#pragma unroll
        for (int p = 0; p < 4; p++) {
            int kl = kk + 8 * p;
            smp[r][kl] = __float2half_rn(W[(size_t)(kbase + kl) * OUTD + n]);
        }
        __syncthreads();
        int r2 = t >> 3, j = t & 7;
        uint2 val = *reinterpret_cast<uint2*>(&smp[r2][j * 4]);
        *reinterpret_cast<uint2*>(&g_w[(size_t)(q * 32 + r2) * KTOT + k0 + j * 4]) = val;
        return;
    }

    // ---- LayerNorm + leaky_relu ----
    int lane = threadIdx.x & 31;
    int row = blockIdx.x * 8 + (threadIdx.x >> 5);

    const float4* xr = reinterpret_cast<const float4*>(x1 + (size_t)row * D1);
    float s = 0.f, q = 0.f;
#pragma unroll
    for (int j = 0; j < 8; j++) {
        float4 t = xr[lane + 32 * j];
        s += t.x + t.y + t.z + t.w;
        q += t.x*t.x + t.y*t.y + t.z*t.z + t.w*t.w;
    }
#pragma unroll
    for (int o = 16; o; o >>= 1) {
        s += __shfl_xor_sync(0xffffffffu, s, o);
        q += __shfl_xor_sync(0xffffffffu, q, o);
    }
    float m = s * (1.f / D1);
    float inv = rsqrtf(q * (1.f / D1) - m * m + 1e-6f);
    __half2* dst = reinterpret_cast<__half2*>(g_f + (size_t)row * KTOT);
#pragma unroll
    for (int j = 0; j < 8; j++) {
        int f = lane + 32 * j;
        float4 t = xr[f];
        float4 sc = reinterpret_cast<const float4*>(s1)[f];
        float4 bi = reinterpret_cast<const float4*>(b1)[f];
        float y0 = leaky((t.x - m) * inv * sc.x + bi.x);
        float y1 = leaky((t.y - m) * inv * sc.y + bi.y);
        float y2 = leaky((t.z - m) * inv * sc.z + bi.z);
        float y3 = leaky((t.w - m) * inv * sc.w + bi.w);
        dst[2 * f]     = __floats2half2_rn(y0, y1);
        dst[2 * f + 1] = __floats2half2_rn(y2, y3);
    }

    const float4* xr2 = reinterpret_cast<const float4*>(x2 + (size_t)row * D2);
    float4 w[4];
    s = 0.f; q = 0.f;
#pragma unroll
    for (int j = 0; j < 4; j++) {
        w[j] = xr2[lane + 32 * j];
        s += w[j].x + w[j].y + w[j].z + w[j].w;
        q += w[j].x*w[j].x + w[j].y*w[j].y + w[j].z*w[j].z + w[j].w*w[j].w;
    }
#pragma unroll
    for (int o = 16; o; o >>= 1) {
        s += __shfl_xor_sync(0xffffffffu, s, o);
        q += __shfl_xor_sync(0xffffffffu, q, o);
    }
    float m2 = s * (1.f / D2);
    float inv2 = rsqrtf(q * (1.f / D2) - m2 * m2 + 1e-6f);
    __half2* dst2 = reinterpret_cast<__half2*>(g_f + (size_t)row * KTOT + D1);
#pragma unroll
    for (int j = 0; j < 4; j++) {
        int f = lane + 32 * j;
        float4 sc = reinterpret_cast<const float4*>(s2)[f];
        float4 bi = reinterpret_cast<const float4*>(b2)[f];
        float y0 = leaky((w[j].x - m2) * inv2 * sc.x + bi.x);
        float y1 = leaky((w[j].y - m2) * inv2 * sc.y + bi.y);
        float y2 = leaky((w[j].z - m2) * inv2 * sc.z + bi.z);
        float y3 = leaky((w[j].w - m2) * inv2 * sc.w + bi.w);
        dst2[2 * f]     = __floats2half2_rn(y0, y1);
        dst2[2 * f + 1] = __floats2half2_rn(y2, y3);
    }
}

// ---------------------------------------------------------------------------
// Kernel 2: mma.sync GEMM 128x128p x K=1536, 256 thr, 8 warps (64x32),
// 3-stage cp.async (96KB -> 2 CTAs/SM), ldmatrix.x4, B-fragment double
// buffering across ks seams, fused gate epilogue (r4 form).
// ---------------------------------------------------------------------------
#define BK 64
#define KIT (KTOT / BK)          // 24
#define ST_A 16384
#define ST_B 16384
#define ST_STRIDE (ST_A + ST_B)  // 32768
#define SMEM_DYN (3 * ST_STRIDE) // 98304

__device__ __forceinline__ uint32_t smem_u32(const void* p) {
    uint32_t a;
    asm("{ .reg .u64 t; cvta.to.shared.u64 t, %1; cvt.u32.u64 %0, t; }" : "=r"(a) : "l"(p));
    return a;
}
__device__ __forceinline__ void mma16816(float* c, const uint32_t* a, const uint32_t* b) {
    asm volatile(
        "mma.sync.aligned.m16n8k16.row.col.f32.f16.f16.f32 "
        "{%0,%1,%2,%3}, {%4,%5,%6,%7}, {%8,%9}, {%0,%1,%2,%3};\n"
        : "+f"(c[0]), "+f"(c[1]), "+f"(c[2]), "+f"(c[3])
        : "r"(a[0]), "r"(a[1]), "r"(a[2]), "r"(a[3]), "r"(b[0]), "r"(b[1]));
}
#define LDSM4(r0, r1, r2, r3, addr) \
    asm volatile("ldmatrix.sync.aligned.m8n8.x4.shared.b16 {%0,%1,%2,%3}, [%4];\n" \
                 : "=r"(r0), "=r"(r1), "=r"(r2), "=r"(r3) : "r"(addr))
#define CPA16(dst, src) \
    asm volatile("cp.async.cg.shared.global [%0], [%1], 16;" :: "r"(dst), "l"(src) : "memory")
#define CP_COMMIT() asm volatile("cp.async.commit_group;" ::: "memory")

__global__ void __launch_bounds__(256, 2) gemm_kernel(
    const float* __restrict__ bo1, const float* __restrict__ bo2,
    const float* __restrict__ bg1, const float* __restrict__ bg2,
    float* __restrict__ out) {
    extern __shared__ char sm[];
    uint32_t base = smem_u32(sm);

    // raster: chunks of 32 mtiles x 16 ntiles -> A+B chunk L2-resident
    int id = blockIdx.x;
    int chunk = id >> 9;
    int rem = id & 511;
    int ntile = rem >> 5;
    int mtile = chunk * 32 + (rem & 31);
    int m0 = mtile * 128;
    int c0 = ntile * 128;

    int tid = threadIdx.x;
    int warp = tid >> 5, lane = tid & 31;
    int wm = (warp & 1) * 64;
    int wn = (warp >> 1) * 32;

    uint32_t aDst[4], bDst[4];
    const __half* aSrc[4];
    const __half* bSrc[4];
#pragma unroll
    for (int i = 0; i < 4; i++) {
        int idx = tid + 256 * i;
        int row = idx >> 3, c = idx & 7;
        uint32_t swz = (uint32_t)(row * 128 + ((c ^ (row & 7)) * 16));
        aDst[i] = base + swz;
        bDst[i] = base + ST_A + swz;
        aSrc[i] = g_f + (size_t)(m0 + row) * KTOT + c * 8;
        bSrc[i] = g_w + (size_t)(c0 + row) * KTOT + c * 8;
    }

#define LOAD_STAGE(j) do { \
        uint32_t _so = (uint32_t)((j) % 3) * ST_STRIDE; \
        size_t _ko = (size_t)(j) * BK; \
        _Pragma("unroll") \
        for (int _i = 0; _i < 4; _i++) { \
            CPA16(aDst[_i] + _so, aSrc[_i] + _ko); \
            CPA16(bDst[_i] + _so, bSrc[_i] + _ko); \
        } \
        CP_COMMIT(); \
    } while (0)

    uint32_t xorv = lane & 7;
    uint32_t aRowOff = (uint32_t)(wm + (lane & 15)) * 128;
    uint32_t aSel = lane >> 4;
    uint32_t bRowOff = (uint32_t)(wn + ((lane >> 4) << 3) + (lane & 7)) * 128;
    uint32_t bSel = (lane >> 3) & 1;

    float acc[4][4][4];
#pragma unroll
    for (int i = 0; i < 4; i++)
#pragma unroll
        for (int j = 0; j < 4; j++)
#pragma unroll
            for (int e = 0; e < 4; e++) acc[i][j][e] = 0.f;

    LOAD_STAGE(0);
    LOAD_STAGE(1);

    for (int kt = 0; kt < KIT; kt++) {
        asm volatile("cp.async.wait_group 1;" ::: "memory");
        __syncthreads();
        if (kt + 2 < KIT) { LOAD_STAGE(kt + 2); }
        else { CP_COMMIT(); }

        uint32_t stA = base + (uint32_t)(kt % 3) * ST_STRIDE;
        uint32_t stB = stA + ST_A;

        // B fragment double buffer: preload ks=0
        uint32_t bcur[4][2], bnxt[4][2];
        {
            uint32_t physB = (bSel ^ xorv) << 4;
            LDSM4(bcur[0][0], bcur[0][1], bcur[1][0], bcur[1][1],
                  stB + bRowOff + physB);
            LDSM4(bcur[2][0], bcur[2][1], bcur[3][0], bcur[3][1],
                  stB + bRowOff + 2048 + physB);
        }
#pragma unroll
        for (int ks = 0; ks < 4; ks++) {
            uint32_t a[4][4];
            uint32_t physA = ((2u * ks + aSel) ^ xorv) << 4;
#pragma unroll
            for (int mi = 0; mi < 4; mi++)
                LDSM4(a[mi][0], a[mi][1], a[mi][2], a[mi][3],
                      stA + aRowOff + mi * 2048 + physA);
            if (ks < 3) {
                uint32_t physB = ((2u * (ks + 1) + bSel) ^ xorv) << 4;
                LDSM4(bnxt[0][0], bnxt[0][1], bnxt[1][0], bnxt[1][1],
                      stB + bRowOff + physB);
                LDSM4(bnxt[2][0], bnxt[2][1], bnxt[3][0], bnxt[3][1],
                      stB + bRowOff + 2048 + physB);
            }
#pragma unroll
            for (int mi = 0; mi < 4; mi++)
#pragma unroll
                for (int nj = 0; nj < 4; nj++)
                    mma16816(acc[mi][nj], a[mi], bcur[nj]);
            if (ks < 3) {
#pragma unroll
                for (int nj = 0; nj < 4; nj++) {
                    bcur[nj][0] = bnxt[nj][0];
                    bcur[nj][1] = bnxt[nj][1];
                }
            }
        }
    }
    __syncthreads();

    // epilogue: gate in regs -> smem (stride 68) -> coalesced float4 stores
    float* ep = reinterpret_cast<float*>(sm);
    {
        int g = lane >> 2, t = lane & 3;
#pragma unroll
        for (int j = 0; j < 2; j++) {
#pragma unroll
            for (int e = 0; e < 4; e++) {
                int nl = (wn >> 1) + j * 8 + t * 2 + (e & 1);
                int n = ntile * 64 + nl;
                float bo = __ldg(bo1 + n) + __ldg(bo2 + n);
                float bg = __ldg(bg1 + n) + __ldg(bg2 + n);
#pragma unroll
                for (int mi = 0; mi < 4; mi++) {
                    int ml = wm + mi * 16 + g + ((e >> 1) * 8);
                    float o = acc[mi][j][e] + bo;
                    float gg = acc[mi][j + 2][e] + bg;
                    ep[ml * 68 + nl] = o * (1.f / (1.f + __expf(-gg)));
                }
            }
        }
    }
    __syncthreads();
    {
        float* outp = out + (size_t)m0 * OUTD + ntile * 64;
#pragma unroll
        for (int qq = 0; qq < 8; qq++) {
            int idx = tid + 256 * qq;
            int row = idx >> 4, c = (idx & 15) * 4;
            const float* src = ep + row * 68 + c;
            float4 v = make_float4(src[0], src[1], src[2], src[3]);
            *reinterpret_cast<float4*>(outp + (size_t)row * OUTD + c) = v;
        }
    }
#undef LOAD_STAGE
}

// ---------------------------------------------------------------------------
extern "C" void kernel_launch(void* const* d_in, const int* in_sizes, int n_in,
                              void* d_out, int out_size) {
    const float* x1  = (const float*)d_in[0];
    const float* x2  = (const float*)d_in[1];
    const float* s1  = (const float*)d_in[2];
    const float* b1  = (const float*)d_in[3];
    const float* s2  = (const float*)d_in[4];
    const float* b2  = (const float*)d_in[5];
    const float* Wo1 = (const float*)d_in[6];
    const float* bo1 = (const float*)d_in[7];
    const float* Wo2 = (const float*)d_in[8];
    const float* bo2 = (const float*)d_in[9];
    const float* Wg1 = (const float*)d_in[10];
    const float* bg1 = (const float*)d_in[11];
    const float* Wg2 = (const float*)d_in[12];
    const float* bg2 = (const float*)d_in[13];
    float* out = (float*)d_out;

    prologue_kernel<<<LN_BLOCKS + PK_BLOCKS, 256>>>(
        x1, x2, s1, b1, s2, b2, Wo1, Wo2, Wg1, Wg2);

    cudaFuncSetAttribute(gemm_kernel,
                         cudaFuncAttributeMaxDynamicSharedMemorySize, SMEM_DYN);
    gemm_kernel<<<(B_ROWS / 128) * (NPACK / 128), 256, SMEM_DYN>>>(
        bo1, bo2, bg1, bg2, out);
}